// round 15
// baseline (speedup 1.0000x reference)
#include <cuda_runtime.h>
#include <math.h>

#define BATCH 2
#define SEQ   2048
#define EMB   1024
#define NH    32
#define KSEL  8
#define HD    128
#define NTOK  (BATCH*SEQ)      // 4096
#define HDALL (NH*HD)          // 4096
#define KD    (KSEL*HD)        // 1024

// ---------------- scratch ----------------
__device__ float g_q[(size_t)BATCH*KSEL*SEQ*HD];   // [B*K, S, D] (tf32-rounded)
__device__ float g_k[(size_t)BATCH*KSEL*SEQ*HD];
__device__ float g_v[(size_t)BATCH*KSEL*SEQ*HD];
__device__ float g_attn[(size_t)NTOK*KD];          // [B,S,K,D] (tf32-rounded)
__device__ float g_xr[(size_t)NTOK*EMB];           // tf32-rounded x
__device__ float g_wq[(size_t)EMB*HDALL];          // tf32-rounded weights
__device__ float g_wk[(size_t)EMB*HDALL];
__device__ float g_wv[(size_t)EMB*HDALL];
__device__ float g_wo[(size_t)KD*EMB];
__device__ int   g_list[NH*NTOK];
__device__ int   g_cnt[NH];
__device__ float g_hw[NTOK*KSEL];
__device__ float g_pacc[BATCH*NH];
__device__ float g_facc[BATCH*NH];
__device__ float g_ent[1];

__device__ __forceinline__ unsigned f2tf(float f) {
    unsigned u;
    asm("cvt.rna.tf32.f32 %0, %1;\n" : "=r"(u) : "f"(f));
    return u;
}
__device__ __forceinline__ float tfround(float f) {
    return __uint_as_float(f2tf(f));
}

__global__ void zero_stats_kernel() {
    int t = threadIdx.x;
    if (t < BATCH*NH) { g_pacc[t] = 0.f; g_facc[t] = 0.f; }
    if (t < NH) g_cnt[t] = 0;
    if (t == 0) g_ent[0] = 0.f;
}

// ---------------- tf32 pre-round passes ----------------
__global__ void tfround_kernel(const float4* __restrict__ src, float4* __restrict__ dst, int n4) {
    int i = blockIdx.x * blockDim.x + threadIdx.x;
    for (; i < n4; i += gridDim.x * blockDim.x) {
        float4 v = src[i];
        v.x = tfround(v.x); v.y = tfround(v.y);
        v.z = tfround(v.z); v.w = tfround(v.w);
        dst[i] = v;
    }
}
// fused for the three equal-size QKV weights
__global__ void tfround3_kernel(const float4* __restrict__ s0, const float4* __restrict__ s1,
                                const float4* __restrict__ s2,
                                float4* __restrict__ d0, float4* __restrict__ d1,
                                float4* __restrict__ d2, int n4) {
    const float4* src = (blockIdx.y == 0) ? s0 : (blockIdx.y == 1) ? s1 : s2;
    float4* dst       = (blockIdx.y == 0) ? d0 : (blockIdx.y == 1) ? d1 : d2;
    int i = blockIdx.x * blockDim.x + threadIdx.x;
    for (; i < n4; i += gridDim.x * blockDim.x) {
        float4 v = src[i];
        v.x = tfround(v.x); v.y = tfround(v.y);
        v.z = tfround(v.z); v.w = tfround(v.w);
        dst[i] = v;
    }
}

// ---------------- router (reads original fp32 x) ----------------
__global__ void router_kernel(const float* __restrict__ x, const float* __restrict__ Wr) {
    __shared__ float xs[EMB];
    __shared__ float lg[NH];
    int tok = blockIdx.x;
    int tid = threadIdx.x;
    const float* xr = x + (size_t)tok * EMB;
    for (int e = tid; e < EMB; e += 32) xs[e] = xr[e];
    __syncwarp();
    float acc = 0.f;
    #pragma unroll 8
    for (int e = 0; e < EMB; e++) acc += xs[e] * Wr[e*NH + tid];
    lg[tid] = acc;
    float m = acc;
    #pragma unroll
    for (int o = 16; o; o >>= 1) m = fmaxf(m, __shfl_xor_sync(0xffffffffu, m, o));
    float ex = expf(acc - m);
    float sum = ex;
    #pragma unroll
    for (int o = 16; o; o >>= 1) sum += __shfl_xor_sync(0xffffffffu, sum, o);
    float p = ex / sum;
    int b = tok / SEQ;
    atomicAdd(&g_pacc[b*NH + tid], p);
    float term = p * logf(p + 1e-8f);
    float esum = term;
    #pragma unroll
    for (int o = 16; o; o >>= 1) esum += __shfl_xor_sync(0xffffffffu, esum, o);
    if (tid == 0) atomicAdd(&g_ent[0], -esum);
    __syncwarp();
    if (tid == 0) {
        float tl[KSEL]; int ti[KSEL];
        unsigned mask = 0;
        for (int k = 0; k < KSEL; k++) {
            float best = -1e30f; int bi = 0;
            for (int h = 0; h < NH; h++)
                if (!((mask >> h) & 1u) && lg[h] > best) { best = lg[h]; bi = h; }
            mask |= 1u << bi; tl[k] = best; ti[k] = bi;
        }
        float ws = 0.f, w[KSEL];
        for (int k = 0; k < KSEL; k++) { w[k] = expf(tl[k] - tl[0]); ws += w[k]; }
        for (int k = 0; k < KSEL; k++) {
            g_hw[tok*KSEL + k] = w[k] / ws;
            int h = ti[k];
            int pos = atomicAdd(&g_cnt[h], 1);
            g_list[h*NTOK + pos] = (tok << 3) | k;
        }
        atomicAdd(&g_facc[b*NH + ti[0]], 1.0f);
    }
}

// ---------------- GEMM common ----------------
#define BM 128
#define BN 128
#define BKt 32
#define LDA 36
#define LDB 132
#define LDC 132

#define CPA16(dst, src) asm volatile("cp.async.cg.shared.global [%0], [%1], 16;\n" \
        :: "r"(dst), "l"(src))
#define CPA_COMMIT() asm volatile("cp.async.commit_group;\n")
#define CPA_WAIT1()  asm volatile("cp.async.wait_group 1;\n")
#define CPA_WAIT0()  asm volatile("cp.async.wait_group 0;\n")

#define MMA_TF32(c0,c1,c2,c3,a0,a1,a2,a3,b0,b1) \
    asm volatile("mma.sync.aligned.m16n8k8.row.col.f32.tf32.tf32.f32 " \
        "{%0,%1,%2,%3}, {%4,%5,%6,%7}, {%8,%9}, {%0,%1,%2,%3};\n" \
        : "+f"(c0), "+f"(c1), "+f"(c2), "+f"(c3) \
        : "r"(a0), "r"(a1), "r"(a2), "r"(a3), "r"(b0), "r"(b1))

// ---------------- grouped projection GEMM: raw tf32 MMA ----------------
__global__ void __launch_bounds__(256, 2) moh_proj_kernel(
    const float* __restrict__ xr,
    const float* __restrict__ Wq, const float* __restrict__ Wk, const float* __restrict__ Wv,
    float* __restrict__ dq, float* __restrict__ dk, float* __restrict__ dv)
{
    int h = blockIdx.y;
    int cnt = g_cnt[h];
    int m0 = blockIdx.x * BM;
    if (m0 >= cnt) return;
    int rows = min(BM, cnt - m0);
    int z = blockIdx.z;
    const float* W = (z == 0) ? Wq : (z == 1) ? Wk : Wv;
    float* dst     = (z == 0) ? dq : (z == 1) ? dk : dv;

    extern __shared__ float sm[];
    float* As[2] = { sm, sm + BM*LDA };
    float* Bs[2] = { sm + 2*BM*LDA, sm + 2*BM*LDA + BKt*LDB };
    float* Csm   = sm;
    __shared__ int s_pk[BM];

    int tid = threadIdx.x;
    if (tid < BM) {
        int r = tid < rows ? tid : rows - 1;
        s_pk[tid] = g_list[h*NTOK + m0 + r];
    }
    __syncthreads();

    int wid = tid >> 5, lane = tid & 31;
    int lr = lane >> 2, lc = lane & 3;
    int wm = wid >> 2, wn = wid & 3;
    int col0 = h * HD;

    int ar[4], ac[4], br[4], bc[4];
    const float* abase[4];
    #pragma unroll
    for (int i = 0; i < 4; i++) {
        int idx = tid + i*256;
        ar[i] = idx >> 3;  ac[i] = (idx & 7) * 4;
        br[i] = idx >> 5;  bc[i] = (idx & 31) * 4;
        abase[i] = xr + (size_t)(s_pk[ar[i]] >> 3) * EMB + ac[i];
    }

    float acc[4][4][4];
    #pragma unroll
    for (int mi = 0; mi < 4; mi++)
        #pragma unroll
        for (int nj = 0; nj < 4; nj++)
            #pragma unroll
            for (int e = 0; e < 4; e++) acc[mi][nj][e] = 0.f;

    const int ntiles = EMB / BKt;
    #pragma unroll
    for (int i = 0; i < 4; i++) {
        unsigned da = (unsigned)__cvta_generic_to_shared(As[0] + ar[i]*LDA + ac[i]);
        CPA16(da, abase[i]);
        unsigned db = (unsigned)__cvta_generic_to_shared(Bs[0] + br[i]*LDB + bc[i]);
        CPA16(db, W + (size_t)br[i] * HDALL + col0 + bc[i]);
    }
    CPA_COMMIT();

    for (int t = 0; t < ntiles; t++) {
        int buf = t & 1;
        if (t + 1 < ntiles) {
            int nb = (t + 1) & 1;
            int k0 = (t + 1) * BKt;
            #pragma unroll
            for (int i = 0; i < 4; i++) {
                unsigned da = (unsigned)__cvta_generic_to_shared(As[nb] + ar[i]*LDA + ac[i]);
                CPA16(da, abase[i] + k0);
                unsigned db = (unsigned)__cvta_generic_to_shared(Bs[nb] + br[i]*LDB + bc[i]);
                CPA16(db, W + (size_t)(k0 + br[i]) * HDALL + col0 + bc[i]);
            }
            CPA_COMMIT();
            CPA_WAIT1();
        } else {
            CPA_WAIT0();
        }
        __syncthreads();

        unsigned* Ab = (unsigned*)As[buf];
        unsigned* Bb = (unsigned*)Bs[buf];
        #pragma unroll
        for (int kk = 0; kk < BKt/8; kk++) {
            int k0 = kk*8;
            unsigned a[4][4];
            #pragma unroll
            for (int mi = 0; mi < 4; mi++) {
                int row = wm*64 + mi*16 + lr;
                a[mi][0] = Ab[row*LDA + k0 + lc];
                a[mi][1] = Ab[(row+8)*LDA + k0 + lc];
                a[mi][2] = Ab[row*LDA + k0 + lc + 4];
                a[mi][3] = Ab[(row+8)*LDA + k0 + lc + 4];
            }
            unsigned b[4][2];
            #pragma unroll
            for (int nj = 0; nj < 4; nj++) {
                int col = wn*32 + nj*8 + lr;
                b[nj][0] = Bb[(k0+lc)*LDB + col];
                b[nj][1] = Bb[(k0+lc+4)*LDB + col];
            }
            #pragma unroll
            for (int mi = 0; mi < 4; mi++)
                #pragma unroll
                for (int nj = 0; nj < 4; nj++)
                    MMA_TF32(acc[mi][nj][0],acc[mi][nj][1],acc[mi][nj][2],acc[mi][nj][3],
                             a[mi][0],a[mi][1],a[mi][2],a[mi][3], b[nj][0],b[nj][1]);
        }
        __syncthreads();
    }

    #pragma unroll
    for (int mi = 0; mi < 4; mi++)
        #pragma unroll
        for (int nj = 0; nj < 4; nj++) {
            int row = wm*64 + mi*16 + lr;
            int col = wn*32 + nj*8 + 2*lc;
            Csm[row*LDC + col]       = acc[mi][nj][0];
            Csm[row*LDC + col + 1]   = acc[mi][nj][1];
            Csm[(row+8)*LDC + col]   = acc[mi][nj][2];
            Csm[(row+8)*LDC + col+1] = acc[mi][nj][3];
        }
    __syncthreads();

    if (z < 2) {
        for (int i = tid; i < BM * 16; i += 256) {
            int row = i >> 4;
            if (row >= rows) break;
            int c4 = (i & 15) * 4;
            int pk = s_pk[row];
            int tok = pk >> 3, j = pk & 7;
            int b = tok / SEQ, s = tok % SEQ;
            float4 lo = *(float4*)&Csm[row*LDC + c4];
            float4 hi = *(float4*)&Csm[row*LDC + c4 + 64];
            float4 olo, ohi;
            float fs = (float)s;
            {
                float cc, sn, ang;
                ang = fs * powf(10000.0f, -(float)(c4+0) / 64.0f);
                cc = cosf(ang); sn = sinf(ang);
                olo.x = tfround(lo.x*cc - hi.x*sn);  ohi.x = tfround(hi.x*cc + lo.x*sn);
                ang = fs * powf(10000.0f, -(float)(c4+1) / 64.0f);
                cc = cosf(ang); sn = sinf(ang);
                olo.y = tfround(lo.y*cc - hi.y*sn);  ohi.y = tfround(hi.y*cc + lo.y*sn);
                ang = fs * powf(10000.0f, -(float)(c4+2) / 64.0f);
                cc = cosf(ang); sn = sinf(ang);
                olo.z = tfround(lo.z*cc - hi.z*sn);  ohi.z = tfround(hi.z*cc + lo.z*sn);
                ang = fs * powf(10000.0f, -(float)(c4+3) / 64.0f);
                cc = cosf(ang); sn = sinf(ang);
                olo.w = tfround(lo.w*cc - hi.w*sn);  ohi.w = tfround(hi.w*cc + lo.w*sn);
            }
            size_t off = (((size_t)(b*KSEL + j)) * SEQ + s) * HD;
            *(float4*)&dst[off + c4]      = olo;
            *(float4*)&dst[off + c4 + 64] = ohi;
        }
    } else {
        for (int i = tid; i < BM * (HD/4); i += 256) {
            int row = i >> 5;
            if (row >= rows) break;
            int c = (i & 31) * 4;
            int pk = s_pk[row];
            int tok = pk >> 3, j = pk & 7;
            int b = tok / SEQ, s = tok % SEQ;
            float4 v = *(float4*)&Csm[row*LDC + c];
            v.x = tfround(v.x); v.y = tfround(v.y);
            v.z = tfround(v.z); v.w = tfround(v.w);
            size_t off = (((size_t)(b*KSEL + j)) * SEQ + s) * HD + c;
            *(float4*)&dst[off] = v;
        }
    }
}

// ---------------- dense GEMM (Wo): raw tf32 MMA ----------------
__global__ void __launch_bounds__(256, 2) tf32_gemm_kernel(
    const float* __restrict__ A, const float* __restrict__ Bm, float* __restrict__ C,
    int M, int N, int Kd)
{
    extern __shared__ float sm[];
    float* As[2] = { sm, sm + BM*LDA };
    float* Bs[2] = { sm + 2*BM*LDA, sm + 2*BM*LDA + BKt*LDB };

    int tid = threadIdx.x;
    int wid = tid >> 5, lane = tid & 31;
    int lr = lane >> 2, lc = lane & 3;
    int wm = wid >> 2, wn = wid & 3;
    int row0 = blockIdx.y * BM, col0 = blockIdx.x * BN;

    int ar[4], ac[4], br[4], bc[4];
    #pragma unroll
    for (int i = 0; i < 4; i++) {
        int idx = tid + i*256;
        ar[i] = idx >> 3;  ac[i] = (idx & 7) * 4;
        br[i] = idx >> 5;  bc[i] = (idx & 31) * 4;
    }

    float acc[4][4][4];
    #pragma unroll
    for (int mi = 0; mi < 4; mi++)
        #pragma unroll
        for (int nj = 0; nj < 4; nj++)
            #pragma unroll
            for (int e = 0; e < 4; e++) acc[mi][nj][e] = 0.f;

    int ntiles = Kd / BKt;
    #pragma unroll
    for (int i = 0; i < 4; i++) {
        unsigned da = (unsigned)__cvta_generic_to_shared(As[0] + ar[i]*LDA + ac[i]);
        CPA16(da, A + (size_t)(row0 + ar[i]) * Kd + ac[i]);
        unsigned db = (unsigned)__cvta_generic_to_shared(Bs[0] + br[i]*LDB + bc[i]);
        CPA16(db, Bm + (size_t)br[i] * N + col0 + bc[i]);
    }
    CPA_COMMIT();

    for (int t = 0; t < ntiles; t++) {
        int buf = t & 1;
        if (t + 1 < ntiles) {
            int nb = (t + 1) & 1;
            int k0 = (t + 1) * BKt;
            #pragma unroll
            for (int i = 0; i < 4; i++) {
                unsigned da = (unsigned)__cvta_generic_to_shared(As[nb] + ar[i]*LDA + ac[i]);
                CPA16(da, A + (size_t)(row0 + ar[i]) * Kd + k0 + ac[i]);
                unsigned db = (unsigned)__cvta_generic_to_shared(Bs[nb] + br[i]*LDB + bc[i]);
                CPA16(db, Bm + (size_t)(k0 + br[i]) * N + col0 + bc[i]);
            }
            CPA_COMMIT();
            CPA_WAIT1();
        } else {
            CPA_WAIT0();
        }
        __syncthreads();

        unsigned* Ab = (unsigned*)As[buf];
        unsigned* Bb = (unsigned*)Bs[buf];
        #pragma unroll
        for (int kk = 0; kk < BKt/8; kk++) {
            int k0 = kk*8;
            unsigned a[4][4];
            #pragma unroll
            for (int mi = 0; mi < 4; mi++) {
                int row = wm*64 + mi*16 + lr;
                a[mi][0] = Ab[row*LDA + k0 + lc];
                a[mi][1] = Ab[(row+8)*LDA + k0 + lc];
                a[mi][2] = Ab[row*LDA + k0 + lc + 4];
                a[mi][3] = Ab[(row+8)*LDA + k0 + lc + 4];
            }
            unsigned b[4][2];
            #pragma unroll
            for (int nj = 0; nj < 4; nj++) {
                int col = wn*32 + nj*8 + lr;
                b[nj][0] = Bb[(k0+lc)*LDB + col];
                b[nj][1] = Bb[(k0+lc+4)*LDB + col];
            }
            #pragma unroll
            for (int mi = 0; mi < 4; mi++)
                #pragma unroll
                for (int nj = 0; nj < 4; nj++)
                    MMA_TF32(acc[mi][nj][0],acc[mi][nj][1],acc[mi][nj][2],acc[mi][nj][3],
                             a[mi][0],a[mi][1],a[mi][2],a[mi][3], b[nj][0],b[nj][1]);
        }
        __syncthreads();
    }

    #pragma unroll
    for (int mi = 0; mi < 4; mi++)
        #pragma unroll
        for (int nj = 0; nj < 4; nj++) {
            int row = row0 + wm*64 + mi*16 + lr;
            int col = col0 + wn*32 + nj*8 + 2*lc;
            *(float2*)&C[(size_t)row * N + col] =
                make_float2(acc[mi][nj][0], acc[mi][nj][1]);
            *(float2*)&C[(size_t)(row+8) * N + col] =
                make_float2(acc[mi][nj][2], acc[mi][nj][3]);
        }
}

// ---------------- TF32 flash attention: pair-processing, 4-stage prefetch ------
// Br=128, Bc=32; warp-row-ownership; 1 syncthreads per KV tile.
#define LQ 132
#define LK 132
#define LV 136
#define LP 36

__global__ void __launch_bounds__(256, 1) flash_tc_kernel(
    const float* __restrict__ Q, const float* __restrict__ Kx, const float* __restrict__ Vx,
    const float* __restrict__ HWp, float* __restrict__ Out)
{
    extern __shared__ float smf[];
    unsigned* Qs    = (unsigned*)smf;           // [128][LQ]
    unsigned* KsBuf = Qs + 128*LQ;              // [4][32][LK]
    unsigned* VsBuf = KsBuf + 4*32*LK;          // [4][32][LV]
    unsigned* Pu    = VsBuf + 4*32*LV;          // [128][LP]

    int tid = threadIdx.x;
    int wid = tid >> 5, lane = tid & 31;
    int lr = lane >> 2, lc = lane & 3;
    int bk = blockIdx.y;
    int q0 = ((int)gridDim.x - 1 - (int)blockIdx.x) * 128;   // heavy-first

    const float* Qp = Q  + (size_t)bk * SEQ * HD;
    const float* Kp = Kx + (size_t)bk * SEQ * HD;
    const float* Vp = Vx + (size_t)bk * SEQ * HD;

    const int nkt = q0/32 + 4;                  // always multiple of 4
    const int npairs = nkt >> 1;
    const int rbase = wid*16 + lr;
    const int gq0 = q0 + rbase, gq1 = gq0 + 8;

    // prologue: prefetch tiles 0,1 into stages 0,1 (single commit group)
    #pragma unroll
    for (int u = 0; u < 2; u++) {
        unsigned* Kd0 = KsBuf + u*32*LK;
        unsigned* Vd0 = VsBuf + u*32*LV;
        for (int i = tid; i < 32 * (HD/4); i += 256) {
            int r = i >> 5, cc = (i & 31) * 4;
            unsigned dk = (unsigned)__cvta_generic_to_shared(&Kd0[r*LK + cc]);
            CPA16(dk, Kp + ((size_t)u*32 + r) * HD + cc);
            unsigned dv = (unsigned)__cvta_generic_to_shared(&Vd0[r*LV + cc]);
            CPA16(dv, Vp + ((size_t)u*32 + r) * HD + cc);
        }
    }
    CPA_COMMIT();

    for (int i = tid; i < 128 * (HD/4); i += 256) {
        int r = i >> 5, cc = (i & 31) * 4;
        *(uint4*)&Qs[r*LQ + cc] = *(const uint4*)(Qp + (size_t)(q0 + r) * HD + cc);
    }

    float o[16][4];
    #pragma unroll
    for (int j = 0; j < 16; j++)
        #pragma unroll
        for (int e = 0; e < 4; e++) o[j][e] = 0.f;
    float m0 = -1e30f, m1 = -1e30f, l0 = 0.f, l1 = 0.f;

    const float scale = 0.08838834764831845f;

    for (int p = 0; p < npairs; p++) {
        int sb = (p & 1) * 2;
        __syncthreads();                       // done reading pair p-1's stages
        if (p + 1 < npairs) {
            int nsb = ((p + 1) & 1) * 2;
            #pragma unroll
            for (int u = 0; u < 2; u++) {
                size_t nb = (size_t)(2*(p + 1) + u) * 32;
                unsigned* Kn = KsBuf + (nsb + u)*32*LK;
                unsigned* Vn = VsBuf + (nsb + u)*32*LV;
                for (int i = tid; i < 32 * (HD/4); i += 256) {
                    int r = i >> 5, cc = (i & 31) * 4;
                    unsigned dk = (unsigned)__cvta_generic_to_shared(&Kn[r*LK + cc]);
                    CPA16(dk, Kp + (nb + r) * HD + cc);
                    unsigned dv = (unsigned)__cvta_generic_to_shared(&Vn[r*LV + cc]);
                    CPA16(dv, Vp + (nb + r) * HD + cc);
                }
            }
            CPA_COMMIT();
            CPA_WAIT1();
        } else {
            CPA_WAIT0();
        }
        __syncthreads();                       // pair p's K/V visible

        #pragma unroll
        for (int u = 0; u < 2; u++) {
            int kt = 2*p + u;
            unsigned* Ks = KsBuf + (sb + u)*32*LK;
            unsigned* Vs = VsBuf + (sb + u)*32*LV;
            int kb = kt * 32;

            // ---- S = Q K^T ----
            float s[4][4];
            #pragma unroll
            for (int nt = 0; nt < 4; nt++)
                #pragma unroll
                for (int e = 0; e < 4; e++) s[nt][e] = 0.f;
            #pragma unroll
            for (int kk = 0; kk < 16; kk++) {
                int k0 = kk*8;
                unsigned a0 = Qs[rbase*LQ + k0 + lc];
                unsigned a1 = Qs[(rbase+8)*LQ + k0 + lc];
                unsigned a2 = Qs[rbase*LQ + k0 + lc + 4];
                unsigned a3 = Qs[(rbase+8)*LQ + k0 + lc + 4];
                #pragma unroll
                for (int nt = 0; nt < 4; nt++) {
                    int nc = nt*8 + lr;
                    unsigned b0 = Ks[nc*LK + k0 + lc];
                    unsigned b1 = Ks[nc*LK + k0 + lc + 4];
                    MMA_TF32(s[nt][0],s[nt][1],s[nt][2],s[nt][3], a0,a1,a2,a3, b0,b1);
                }
            }

            // ---- warp-local online softmax ----
            {
                int lim0 = gq0 - kb;
                int lim1 = gq1 - kb;
                float p0[8], p1[8];
                float mx0 = -1e30f, mx1 = -1e30f;
                #pragma unroll
                for (int nt = 0; nt < 4; nt++) {
                    int c0 = nt*8 + 2*lc, c1 = c0 + 1;
                    p0[nt*2]   = (c0 <= lim0) ? s[nt][0]*scale : -1e30f;
                    p0[nt*2+1] = (c1 <= lim0) ? s[nt][1]*scale : -1e30f;
                    p1[nt*2]   = (c0 <= lim1) ? s[nt][2]*scale : -1e30f;
                    p1[nt*2+1] = (c1 <= lim1) ? s[nt][3]*scale : -1e30f;
                    mx0 = fmaxf(mx0, fmaxf(p0[nt*2], p0[nt*2+1]));
                    mx1 = fmaxf(mx1, fmaxf(p1[nt*2], p1[nt*2+1]));
                }
                mx0 = fmaxf(mx0, __shfl_xor_sync(0xffffffffu, mx0, 1));
                mx0 = fmaxf(mx0, __shfl_xor_sync(0xffffffffu, mx0, 2));
                mx1 = fmaxf(mx1, __shfl_xor_sync(0xffffffffu, mx1, 1));
                mx1 = fmaxf(mx1, __shfl_xor_sync(0xffffffffu, mx1, 2));
                float mn0 = fmaxf(m0, mx0), mn1 = fmaxf(m1, mx1);
                float al0 = __expf(m0 - mn0), al1 = __expf(m1 - mn1);
                float ss0 = 0.f, ss1 = 0.f;
                #pragma unroll
                for (int nt = 0; nt < 4; nt++) {
                    int c0 = nt*8 + 2*lc, c1 = c0 + 1;
                    float e00 = (c0 <= lim0) ? __expf(p0[nt*2]   - mn0) : 0.f;
                    float e01 = (c1 <= lim0) ? __expf(p0[nt*2+1] - mn0) : 0.f;
                    float e10 = (c0 <= lim1) ? __expf(p1[nt*2]   - mn1) : 0.f;
                    float e11 = (c1 <= lim1) ? __expf(p1[nt*2+1] - mn1) : 0.f;
                    Pu[rbase*LP + c0]     = f2tf(e00);
                    Pu[rbase*LP + c1]     = f2tf(e01);
                    Pu[(rbase+8)*LP + c0] = f2tf(e10);
                    Pu[(rbase+8)*LP + c1] = f2tf(e11);
                    ss0 += e00 + e01;
                    ss1 += e10 + e11;
                }
                ss0 += __shfl_xor_sync(0xffffffffu, ss0, 1);
                ss0 += __shfl_xor_sync(0xffffffffu, ss0, 2);
                ss1 += __shfl_xor_sync(0xffffffffu, ss1, 1);
                ss1 += __shfl_xor_sync(0xffffffffu, ss1, 2);
                l0 = l0 * al0 + ss0;  m0 = mn0;
                l1 = l1 * al1 + ss1;  m1 = mn1;
                #pragma unroll
                for (int j = 0; j < 16; j++) {
                    o[j][0] *= al0; o[j][1] *= al0;
                    o[j][2] *= al1; o[j][3] *= al1;
                }
            }
            __syncwarp();                      // P visible within warp

            // ---- O += P V ----
            #pragma unroll
            for (int kk = 0; kk < 4; kk++) {
                int k0 = kk*8;
                unsigned a0 = Pu[rbase*LP + k0 + lc];
                unsigned a1 = Pu[(rbase+8)*LP + k0 + lc];
                unsigned a2 = Pu[rbase*LP + k0 + lc + 4];
                unsigned a3 = Pu[(rbase+8)*LP + k0 + lc + 4];
                #pragma unroll
                for (int j = 0; j < 16; j++) {
                    int vc = j*8 + lr;
                    unsigned b0 = Vs[(k0 + lc)*LV + vc];
                    unsigned b1 = Vs[(k0 + lc + 4)*LV + vc];
                    MMA_TF32(o[j][0],o[j][1],o[j][2],o[j][3], a0,a1,a2,a3, b0,b1);
                }
            }
            __syncwarp();                      // P reads done before next tile's writes
        }
    }

    // ---- epilogue (tf32-rounded for the Wo GEMM) ----
    int b = bk >> 3, jslot = bk & 7;
    float w_lo = HWp[((size_t)(b*SEQ + gq0)) * KSEL + jslot] / l0;
    float w_hi = HWp[((size_t)(b*SEQ + gq1)) * KSEL + jslot] / l1;
    #pragma unroll
    for (int j = 0; j < 16; j++) {
        int cb = j*8 + 2*lc;
        size_t off0 = (((size_t)(b*SEQ + gq0)) * KSEL + jslot) * HD + cb;
        size_t off1 = (((size_t)(b*SEQ + gq1)) * KSEL + jslot) * HD + cb;
        float2 v0 = make_float2(tfround(o[j][0]*w_lo), tfround(o[j][1]*w_lo));
        float2 v1 = make_float2(tfround(o[j][2]*w_hi), tfround(o[j][3]*w_hi));
        *(float2*)&Out[off0] = v0;
        *(float2*)&Out[off1] = v1;
    }
}

// ---------------- aux loss + head_counts tail ----------------
__global__ void finalize_kernel(float* __restrict__ out, int out_size) {
    int base = NTOK * EMB;
    int extra = out_size - base;
    if (extra <= 0) return;
    bool has_aux = (extra == BATCH*NH + 1) || (extra == 1);
    int zend = has_aux ? out_size - 1 : out_size;
    int gtid = blockIdx.x * blockDim.x + threadIdx.x;
    for (int i = base + gtid; i < zend; i += gridDim.x * blockDim.x) out[i] = 0.f;
    if (gtid == 0 && has_aux) {
        float aux = 0.f;
        for (int b = 0; b < BATCH; b++) {
            float sb = 0.f;
            for (int h = 0; h < NH; h++)
                sb += (g_facc[b*NH + h] / (float)SEQ) * (g_pacc[b*NH + h] / (float)SEQ);
            aux += sb;
        }
        aux = (float)NH * aux / (float)BATCH - 0.01f * (g_ent[0] / (float)(BATCH*SEQ));
        out[out_size - 1] = aux;
    }
}

// ---------------- launcher ----------------
extern "C" void kernel_launch(void* const* d_in, const int* in_sizes, int n_in,
                              void* d_out, int out_size)
{
    (void)in_sizes; (void)n_in;
    const float* x  = (const float*)d_in[0];
    const float* Wq = (const float*)d_in[1];
    const float* Wk = (const float*)d_in[2];
    const float* Wv = (const float*)d_in[3];
    const float* Wr = (const float*)d_in[4];
    const float* Wo = (const float*)d_in[5];
    float* out = (float*)d_out;

    float *p_q, *p_k, *p_v, *p_attn, *p_hw;
    float *p_xr, *p_wq, *p_wk, *p_wv, *p_wo;
    cudaGetSymbolAddress((void**)&p_q,    g_q);
    cudaGetSymbolAddress((void**)&p_k,    g_k);
    cudaGetSymbolAddress((void**)&p_v,    g_v);
    cudaGetSymbolAddress((void**)&p_attn, g_attn);
    cudaGetSymbolAddress((void**)&p_hw,   g_hw);
    cudaGetSymbolAddress((void**)&p_xr,   g_xr);
    cudaGetSymbolAddress((void**)&p_wq,   g_wq);
    cudaGetSymbolAddress((void**)&p_wk,   g_wk);
    cudaGetSymbolAddress((void**)&p_wv,   g_wv);
    cudaGetSymbolAddress((void**)&p_wo,   g_wo);

    size_t gemm_smem = (size_t)(2*BM*LDA + 2*BKt*LDB) * sizeof(float);
    cudaFuncSetAttribute(moh_proj_kernel, cudaFuncAttributeMaxDynamicSharedMemorySize,
                         (int)gemm_smem);
    cudaFuncSetAttribute(tf32_gemm_kernel, cudaFuncAttributeMaxDynamicSharedMemorySize,
                         (int)gemm_smem);
    size_t flash_smem = (size_t)(128*LQ + 4*32*LK + 4*32*LV + 128*LP) * sizeof(float);
    cudaFuncSetAttribute(flash_tc_kernel, cudaFuncAttributeMaxDynamicSharedMemorySize,
                         (int)flash_smem);

    zero_stats_kernel<<<1, 128>>>();
    router_kernel<<<NTOK, 32>>>(x, Wr);

    // pre-round inputs/weights to tf32
    tfround_kernel<<<512, 256>>>((const float4*)x,  (float4*)p_xr, NTOK*EMB/4);
    dim3 g3(512, 3);
    tfround3_kernel<<<g3, 256>>>((const float4*)Wq, (const float4*)Wk, (const float4*)Wv,
                                 (float4*)p_wq, (float4*)p_wk, (float4*)p_wv, EMB*HDALL/4);
    tfround_kernel<<<512, 256>>>((const float4*)Wo, (float4*)p_wo, KD*EMB/4);

    dim3 gproj(NTOK/BM, NH, 3);
    moh_proj_kernel<<<gproj, 256, gemm_smem>>>(p_xr, p_wq, p_wk, p_wv, p_q, p_k, p_v);

    dim3 gflash(SEQ/128, BATCH*KSEL);   // (16, 16)
    flash_tc_kernel<<<gflash, 256, flash_smem>>>(p_q, p_k, p_v, p_hw, p_attn);

    dim3 gout(EMB/BN, NTOK/BM);
    tf32_gemm_kernel<<<gout, 256, gemm_smem>>>(p_attn, p_wo, out, NTOK, EMB, EMB);

    finalize_kernel<<<32, 256>>>(out, out_size);
}

// round 17
// speedup vs baseline: 1.0745x; 1.0745x over previous
#include <cuda_runtime.h>
#include <math.h>

#define BATCH 2
#define SEQ   2048
#define EMB   1024
#define NH    32
#define KSEL  8
#define HD    128
#define NTOK  (BATCH*SEQ)      // 4096
#define HDALL (NH*HD)          // 4096
#define KD    (KSEL*HD)        // 1024

// ---------------- scratch ----------------
__device__ float g_q[(size_t)BATCH*KSEL*SEQ*HD];   // [B*K, S, D] (tf32-rounded)
__device__ float g_k[(size_t)BATCH*KSEL*SEQ*HD];
__device__ float g_v[(size_t)BATCH*KSEL*SEQ*HD];
__device__ float g_attn[(size_t)NTOK*KD];          // [B,S,K,D] (tf32-rounded)
__device__ float g_xr[(size_t)NTOK*EMB];           // tf32-rounded x
__device__ float g_wq[(size_t)EMB*HDALL];          // tf32-rounded weights
__device__ float g_wk[(size_t)EMB*HDALL];
__device__ float g_wv[(size_t)EMB*HDALL];
__device__ float g_wo[(size_t)KD*EMB];
__device__ int   g_list[NH*NTOK];
__device__ int   g_cnt[NH];
__device__ float g_hw[NTOK*KSEL];
__device__ float g_pacc[BATCH*NH];
__device__ float g_facc[BATCH*NH];
__device__ float g_ent[1];

__device__ __forceinline__ unsigned f2tf(float f) {
    unsigned u;
    asm("cvt.rna.tf32.f32 %0, %1;\n" : "=r"(u) : "f"(f));
    return u;
}
__device__ __forceinline__ float tfround(float f) {
    return __uint_as_float(f2tf(f));
}

__global__ void zero_stats_kernel() {
    int t = threadIdx.x;
    if (t < BATCH*NH) { g_pacc[t] = 0.f; g_facc[t] = 0.f; }
    if (t < NH) g_cnt[t] = 0;
    if (t == 0) g_ent[0] = 0.f;
}

// ---------------- tf32 pre-round passes ----------------
__global__ void tfround_kernel(const float4* __restrict__ src, float4* __restrict__ dst, int n4) {
    int i = blockIdx.x * blockDim.x + threadIdx.x;
    for (; i < n4; i += gridDim.x * blockDim.x) {
        float4 v = src[i];
        v.x = tfround(v.x); v.y = tfround(v.y);
        v.z = tfround(v.z); v.w = tfround(v.w);
        dst[i] = v;
    }
}
__global__ void tfround3_kernel(const float4* __restrict__ s0, const float4* __restrict__ s1,
                                const float4* __restrict__ s2,
                                float4* __restrict__ d0, float4* __restrict__ d1,
                                float4* __restrict__ d2, int n4) {
    const float4* src = (blockIdx.y == 0) ? s0 : (blockIdx.y == 1) ? s1 : s2;
    float4* dst       = (blockIdx.y == 0) ? d0 : (blockIdx.y == 1) ? d1 : d2;
    int i = blockIdx.x * blockDim.x + threadIdx.x;
    for (; i < n4; i += gridDim.x * blockDim.x) {
        float4 v = src[i];
        v.x = tfround(v.x); v.y = tfround(v.y);
        v.z = tfround(v.z); v.w = tfround(v.w);
        dst[i] = v;
    }
}

// ---------------- router: 128 threads, 4-way split dot ----------------
__global__ void router_kernel(const float* __restrict__ x, const float* __restrict__ Wr) {
    __shared__ float xs[EMB];
    __shared__ float red[4][NH];
    __shared__ float lg[NH];
    int tok = blockIdx.x;
    int tid = threadIdx.x;                 // 128
    int grp = tid >> 5, lane = tid & 31;   // grp: e-range, lane: head
    const float* xr = x + (size_t)tok * EMB;
    for (int e = tid; e < EMB; e += 128) xs[e] = xr[e];
    __syncthreads();
    float acc = 0.f;
    int e0 = grp * 256;
    #pragma unroll 8
    for (int e = 0; e < 256; e++) acc += xs[e0 + e] * Wr[(e0 + e)*NH + lane];
    red[grp][lane] = acc;
    __syncthreads();
    if (tid < 32) {
        float v = red[0][tid] + red[1][tid] + red[2][tid] + red[3][tid];
        lg[tid] = v;
        float m = v;
        #pragma unroll
        for (int o = 16; o; o >>= 1) m = fmaxf(m, __shfl_xor_sync(0xffffffffu, m, o));
        float ex = expf(v - m);
        float sum = ex;
        #pragma unroll
        for (int o = 16; o; o >>= 1) sum += __shfl_xor_sync(0xffffffffu, sum, o);
        float p = ex / sum;
        int b = tok / SEQ;
        atomicAdd(&g_pacc[b*NH + tid], p);
        float term = p * logf(p + 1e-8f);
        float esum = term;
        #pragma unroll
        for (int o = 16; o; o >>= 1) esum += __shfl_xor_sync(0xffffffffu, esum, o);
        if (tid == 0) atomicAdd(&g_ent[0], -esum);
        __syncwarp();
        if (tid == 0) {
            float tl[KSEL]; int ti[KSEL];
            unsigned mask = 0;
            for (int k = 0; k < KSEL; k++) {
                float best = -1e30f; int bi = 0;
                for (int h = 0; h < NH; h++)
                    if (!((mask >> h) & 1u) && lg[h] > best) { best = lg[h]; bi = h; }
                mask |= 1u << bi; tl[k] = best; ti[k] = bi;
            }
            float ws = 0.f, w[KSEL];
            for (int k = 0; k < KSEL; k++) { w[k] = expf(tl[k] - tl[0]); ws += w[k]; }
            for (int k = 0; k < KSEL; k++) {
                g_hw[tok*KSEL + k] = w[k] / ws;
                int h = ti[k];
                int pos = atomicAdd(&g_cnt[h], 1);
                g_list[h*NTOK + pos] = (tok << 3) | k;
            }
            atomicAdd(&g_facc[b*NH + ti[0]], 1.0f);
        }
    }
}

// ---------------- GEMM common ----------------
#define BM 128
#define BN 128
#define BKt 32
#define LDA 36
#define LDB 132
#define LDC 132

#define CPA16(dst, src) asm volatile("cp.async.cg.shared.global [%0], [%1], 16;\n" \
        :: "r"(dst), "l"(src))
#define CPA_COMMIT() asm volatile("cp.async.commit_group;\n")
#define CPA_WAIT1()  asm volatile("cp.async.wait_group 1;\n")
#define CPA_WAIT0()  asm volatile("cp.async.wait_group 0;\n")

#define MMA_TF32(c0,c1,c2,c3,a0,a1,a2,a3,b0,b1) \
    asm volatile("mma.sync.aligned.m16n8k8.row.col.f32.tf32.tf32.f32 " \
        "{%0,%1,%2,%3}, {%4,%5,%6,%7}, {%8,%9}, {%0,%1,%2,%3};\n" \
        : "+f"(c0), "+f"(c1), "+f"(c2), "+f"(c3) \
        : "r"(a0), "r"(a1), "r"(a2), "r"(a3), "r"(b0), "r"(b1))

// ---------------- grouped projection GEMM: raw tf32 MMA ----------------
__global__ void __launch_bounds__(256, 2) moh_proj_kernel(
    const float* __restrict__ xr,
    const float* __restrict__ Wq, const float* __restrict__ Wk, const float* __restrict__ Wv,
    float* __restrict__ dq, float* __restrict__ dk, float* __restrict__ dv)
{
    int h = blockIdx.y;
    int cnt = g_cnt[h];
    int m0 = blockIdx.x * BM;
    if (m0 >= cnt) return;
    int rows = min(BM, cnt - m0);
    int z = blockIdx.z;
    const float* W = (z == 0) ? Wq : (z == 1) ? Wk : Wv;
    float* dst     = (z == 0) ? dq : (z == 1) ? dk : dv;

    extern __shared__ float sm[];
    float* As[2] = { sm, sm + BM*LDA };
    float* Bs[2] = { sm + 2*BM*LDA, sm + 2*BM*LDA + BKt*LDB };
    float* Csm   = sm;
    __shared__ int s_pk[BM];

    int tid = threadIdx.x;
    if (tid < BM) {
        int r = tid < rows ? tid : rows - 1;
        s_pk[tid] = g_list[h*NTOK + m0 + r];
    }
    __syncthreads();

    int wid = tid >> 5, lane = tid & 31;
    int lr = lane >> 2, lc = lane & 3;
    int wm = wid >> 2, wn = wid & 3;
    int col0 = h * HD;

    int ar[4], ac[4], br[4], bc[4];
    const float* abase[4];
    #pragma unroll
    for (int i = 0; i < 4; i++) {
        int idx = tid + i*256;
        ar[i] = idx >> 3;  ac[i] = (idx & 7) * 4;
        br[i] = idx >> 5;  bc[i] = (idx & 31) * 4;
        abase[i] = xr + (size_t)(s_pk[ar[i]] >> 3) * EMB + ac[i];
    }

    float acc[4][4][4];
    #pragma unroll
    for (int mi = 0; mi < 4; mi++)
        #pragma unroll
        for (int nj = 0; nj < 4; nj++)
            #pragma unroll
            for (int e = 0; e < 4; e++) acc[mi][nj][e] = 0.f;

    const int ntiles = EMB / BKt;
    #pragma unroll
    for (int i = 0; i < 4; i++) {
        unsigned da = (unsigned)__cvta_generic_to_shared(As[0] + ar[i]*LDA + ac[i]);
        CPA16(da, abase[i]);
        unsigned db = (unsigned)__cvta_generic_to_shared(Bs[0] + br[i]*LDB + bc[i]);
        CPA16(db, W + (size_t)br[i] * HDALL + col0 + bc[i]);
    }
    CPA_COMMIT();

    for (int t = 0; t < ntiles; t++) {
        int buf = t & 1;
        if (t + 1 < ntiles) {
            int nb = (t + 1) & 1;
            int k0 = (t + 1) * BKt;
            #pragma unroll
            for (int i = 0; i < 4; i++) {
                unsigned da = (unsigned)__cvta_generic_to_shared(As[nb] + ar[i]*LDA + ac[i]);
                CPA16(da, abase[i] + k0);
                unsigned db = (unsigned)__cvta_generic_to_shared(Bs[nb] + br[i]*LDB + bc[i]);
                CPA16(db, W + (size_t)(k0 + br[i]) * HDALL + col0 + bc[i]);
            }
            CPA_COMMIT();
            CPA_WAIT1();
        } else {
            CPA_WAIT0();
        }
        __syncthreads();

        unsigned* Ab = (unsigned*)As[buf];
        unsigned* Bb = (unsigned*)Bs[buf];
        #pragma unroll
        for (int kk = 0; kk < BKt/8; kk++) {
            int k0 = kk*8;
            unsigned a[4][4];
            #pragma unroll
            for (int mi = 0; mi < 4; mi++) {
                int row = wm*64 + mi*16 + lr;
                a[mi][0] = Ab[row*LDA + k0 + lc];
                a[mi][1] = Ab[(row+8)*LDA + k0 + lc];
                a[mi][2] = Ab[row*LDA + k0 + lc + 4];
                a[mi][3] = Ab[(row+8)*LDA + k0 + lc + 4];
            }
            unsigned b[4][2];
            #pragma unroll
            for (int nj = 0; nj < 4; nj++) {
                int col = wn*32 + nj*8 + lr;
                b[nj][0] = Bb[(k0+lc)*LDB + col];
                b[nj][1] = Bb[(k0+lc+4)*LDB + col];
            }
            #pragma unroll
            for (int mi = 0; mi < 4; mi++)
                #pragma unroll
                for (int nj = 0; nj < 4; nj++)
                    MMA_TF32(acc[mi][nj][0],acc[mi][nj][1],acc[mi][nj][2],acc[mi][nj][3],
                             a[mi][0],a[mi][1],a[mi][2],a[mi][3], b[nj][0],b[nj][1]);
        }
        __syncthreads();
    }

    #pragma unroll
    for (int mi = 0; mi < 4; mi++)
        #pragma unroll
        for (int nj = 0; nj < 4; nj++) {
            int row = wm*64 + mi*16 + lr;
            int col = wn*32 + nj*8 + 2*lc;
            Csm[row*LDC + col]       = acc[mi][nj][0];
            Csm[row*LDC + col + 1]   = acc[mi][nj][1];
            Csm[(row+8)*LDC + col]   = acc[mi][nj][2];
            Csm[(row+8)*LDC + col+1] = acc[mi][nj][3];
        }
    __syncthreads();

    if (z < 2) {
        for (int i = tid; i < BM * 16; i += 256) {
            int row = i >> 4;
            if (row >= rows) break;
            int c4 = (i & 15) * 4;
            int pk = s_pk[row];
            int tok = pk >> 3, j = pk & 7;
            int b = tok / SEQ, s = tok % SEQ;
            float4 lo = *(float4*)&Csm[row*LDC + c4];
            float4 hi = *(float4*)&Csm[row*LDC + c4 + 64];
            float4 olo, ohi;
            float fs = (float)s;
            {
                float cc, sn, ang;
                ang = fs * powf(10000.0f, -(float)(c4+0) / 64.0f);
                cc = cosf(ang); sn = sinf(ang);
                olo.x = tfround(lo.x*cc - hi.x*sn);  ohi.x = tfround(hi.x*cc + lo.x*sn);
                ang = fs * powf(10000.0f, -(float)(c4+1) / 64.0f);
                cc = cosf(ang); sn = sinf(ang);
                olo.y = tfround(lo.y*cc - hi.y*sn);  ohi.y = tfround(hi.y*cc + lo.y*sn);
                ang = fs * powf(10000.0f, -(float)(c4+2) / 64.0f);
                cc = cosf(ang); sn = sinf(ang);
                olo.z = tfround(lo.z*cc - hi.z*sn);  ohi.z = tfround(hi.z*cc + lo.z*sn);
                ang = fs * powf(10000.0f, -(float)(c4+3) / 64.0f);
                cc = cosf(ang); sn = sinf(ang);
                olo.w = tfround(lo.w*cc - hi.w*sn);  ohi.w = tfround(hi.w*cc + lo.w*sn);
            }
            size_t off = (((size_t)(b*KSEL + j)) * SEQ + s) * HD;
            *(float4*)&dst[off + c4]      = olo;
            *(float4*)&dst[off + c4 + 64] = ohi;
        }
    } else {
        for (int i = tid; i < BM * (HD/4); i += 256) {
            int row = i >> 5;
            if (row >= rows) break;
            int c = (i & 31) * 4;
            int pk = s_pk[row];
            int tok = pk >> 3, j = pk & 7;
            int b = tok / SEQ, s = tok % SEQ;
            float4 v = *(float4*)&Csm[row*LDC + c];
            v.x = tfround(v.x); v.y = tfround(v.y);
            v.z = tfround(v.z); v.w = tfround(v.w);
            size_t off = (((size_t)(b*KSEL + j)) * SEQ + s) * HD + c;
            *(float4*)&dst[off] = v;
        }
    }
}

// ---------------- dense GEMM (Wo): raw tf32 MMA ----------------
__global__ void __launch_bounds__(256, 2) tf32_gemm_kernel(
    const float* __restrict__ A, const float* __restrict__ Bm, float* __restrict__ C,
    int M, int N, int Kd)
{
    extern __shared__ float sm[];
    float* As[2] = { sm, sm + BM*LDA };
    float* Bs[2] = { sm + 2*BM*LDA, sm + 2*BM*LDA + BKt*LDB };

    int tid = threadIdx.x;
    int wid = tid >> 5, lane = tid & 31;
    int lr = lane >> 2, lc = lane & 3;
    int wm = wid >> 2, wn = wid & 3;
    int row0 = blockIdx.y * BM, col0 = blockIdx.x * BN;

    int ar[4], ac[4], br[4], bc[4];
    #pragma unroll
    for (int i = 0; i < 4; i++) {
        int idx = tid + i*256;
        ar[i] = idx >> 3;  ac[i] = (idx & 7) * 4;
        br[i] = idx >> 5;  bc[i] = (idx & 31) * 4;
    }

    float acc[4][4][4];
    #pragma unroll
    for (int mi = 0; mi < 4; mi++)
        #pragma unroll
        for (int nj = 0; nj < 4; nj++)
            #pragma unroll
            for (int e = 0; e < 4; e++) acc[mi][nj][e] = 0.f;

    int ntiles = Kd / BKt;
    #pragma unroll
    for (int i = 0; i < 4; i++) {
        unsigned da = (unsigned)__cvta_generic_to_shared(As[0] + ar[i]*LDA + ac[i]);
        CPA16(da, A + (size_t)(row0 + ar[i]) * Kd + ac[i]);
        unsigned db = (unsigned)__cvta_generic_to_shared(Bs[0] + br[i]*LDB + bc[i]);
        CPA16(db, Bm + (size_t)br[i] * N + col0 + bc[i]);
    }
    CPA_COMMIT();

    for (int t = 0; t < ntiles; t++) {
        int buf = t & 1;
        if (t + 1 < ntiles) {
            int nb = (t + 1) & 1;
            int k0 = (t + 1) * BKt;
            #pragma unroll
            for (int i = 0; i < 4; i++) {
                unsigned da = (unsigned)__cvta_generic_to_shared(As[nb] + ar[i]*LDA + ac[i]);
                CPA16(da, A + (size_t)(row0 + ar[i]) * Kd + k0 + ac[i]);
                unsigned db = (unsigned)__cvta_generic_to_shared(Bs[nb] + br[i]*LDB + bc[i]);
                CPA16(db, Bm + (size_t)(k0 + br[i]) * N + col0 + bc[i]);
            }
            CPA_COMMIT();
            CPA_WAIT1();
        } else {
            CPA_WAIT0();
        }
        __syncthreads();

        unsigned* Ab = (unsigned*)As[buf];
        unsigned* Bb = (unsigned*)Bs[buf];
        #pragma unroll
        for (int kk = 0; kk < BKt/8; kk++) {
            int k0 = kk*8;
            unsigned a[4][4];
            #pragma unroll
            for (int mi = 0; mi < 4; mi++) {
                int row = wm*64 + mi*16 + lr;
                a[mi][0] = Ab[row*LDA + k0 + lc];
                a[mi][1] = Ab[(row+8)*LDA + k0 + lc];
                a[mi][2] = Ab[row*LDA + k0 + lc + 4];
                a[mi][3] = Ab[(row+8)*LDA + k0 + lc + 4];
            }
            unsigned b[4][2];
            #pragma unroll
            for (int nj = 0; nj < 4; nj++) {
                int col = wn*32 + nj*8 + lr;
                b[nj][0] = Bb[(k0+lc)*LDB + col];
                b[nj][1] = Bb[(k0+lc+4)*LDB + col];
            }
            #pragma unroll
            for (int mi = 0; mi < 4; mi++)
                #pragma unroll
                for (int nj = 0; nj < 4; nj++)
                    MMA_TF32(acc[mi][nj][0],acc[mi][nj][1],acc[mi][nj][2],acc[mi][nj][3],
                             a[mi][0],a[mi][1],a[mi][2],a[mi][3], b[nj][0],b[nj][1]);
        }
        __syncthreads();
    }

    #pragma unroll
    for (int mi = 0; mi < 4; mi++)
        #pragma unroll
        for (int nj = 0; nj < 4; nj++) {
            int row = row0 + wm*64 + mi*16 + lr;
            int col = col0 + wn*32 + nj*8 + 2*lc;
            *(float2*)&C[(size_t)row * N + col] =
                make_float2(acc[mi][nj][0], acc[mi][nj][1]);
            *(float2*)&C[(size_t)(row+8) * N + col] =
                make_float2(acc[mi][nj][2], acc[mi][nj][3]);
        }
}

// ---------------- TF32 flash attention (2-stage, warp-row-ownership) ----
#define LQ 132
#define LK 132
#define LV 136
#define LP 36

__global__ void __launch_bounds__(256, 1) flash_tc_kernel(
    const float* __restrict__ Q, const float* __restrict__ Kx, const float* __restrict__ Vx,
    const float* __restrict__ HWp, float* __restrict__ Out)
{
    extern __shared__ float smf[];
    unsigned* Qs    = (unsigned*)smf;           // [128][LQ]
    unsigned* KsBuf = Qs + 128*LQ;              // [2][32][LK]
    unsigned* VsBuf = KsBuf + 2*32*LK;          // [2][32][LV]
    unsigned* Pu    = VsBuf + 2*32*LV;          // [128][LP]

    int tid = threadIdx.x;
    int wid = tid >> 5, lane = tid & 31;
    int lr = lane >> 2, lc = lane & 3;
    int bk = blockIdx.y;
    int q0 = ((int)gridDim.x - 1 - (int)blockIdx.x) * 128;   // heavy-first

    const float* Qp = Q  + (size_t)bk * SEQ * HD;
    const float* Kp = Kx + (size_t)bk * SEQ * HD;
    const float* Vp = Vx + (size_t)bk * SEQ * HD;

    const int nkt = q0/32 + 4;
    const int rbase = wid*16 + lr;
    const int gq0 = q0 + rbase, gq1 = gq0 + 8;

    for (int i = tid; i < 32 * (HD/4); i += 256) {
        int r = i >> 5, cc = (i & 31) * 4;
        unsigned dk = (unsigned)__cvta_generic_to_shared(&KsBuf[r*LK + cc]);
        CPA16(dk, Kp + (size_t)r * HD + cc);
        unsigned dv = (unsigned)__cvta_generic_to_shared(&VsBuf[r*LV + cc]);
        CPA16(dv, Vp + (size_t)r * HD + cc);
    }
    CPA_COMMIT();

    for (int i = tid; i < 128 * (HD/4); i += 256) {
        int r = i >> 5, cc = (i & 31) * 4;
        *(uint4*)&Qs[r*LQ + cc] = *(const uint4*)(Qp + (size_t)(q0 + r) * HD + cc);
    }

    float o[16][4];
    #pragma unroll
    for (int j = 0; j < 16; j++)
        #pragma unroll
        for (int e = 0; e < 4; e++) o[j][e] = 0.f;
    float m0 = -1e30f, m1 = -1e30f, l0 = 0.f, l1 = 0.f;

    const float scale = 0.08838834764831845f;

    for (int kt = 0; kt < nkt; kt++) {
        int stage = kt & 1;
        __syncthreads();
        if (kt + 1 < nkt) {
            int ns = stage ^ 1;
            size_t nb = (size_t)(kt + 1) * 32;
            unsigned* Kn = KsBuf + ns*32*LK;
            unsigned* Vn = VsBuf + ns*32*LV;
            for (int i = tid; i < 32 * (HD/4); i += 256) {
                int r = i >> 5, cc = (i & 31) * 4;
                unsigned dk = (unsigned)__cvta_generic_to_shared(&Kn[r*LK + cc]);
                CPA16(dk, Kp + (nb + r) * HD + cc);
                unsigned dv = (unsigned)__cvta_generic_to_shared(&Vn[r*LV + cc]);
                CPA16(dv, Vp + (nb + r) * HD + cc);
            }
            CPA_COMMIT();
            CPA_WAIT1();
        } else {
            CPA_WAIT0();
        }
        __syncthreads();

        unsigned* Ks = KsBuf + stage*32*LK;
        unsigned* Vs = VsBuf + stage*32*LV;
        int kb = kt * 32;

        float s[4][4];
        #pragma unroll
        for (int nt = 0; nt < 4; nt++)
            #pragma unroll
            for (int e = 0; e < 4; e++) s[nt][e] = 0.f;
        #pragma unroll
        for (int kk = 0; kk < 16; kk++) {
            int k0 = kk*8;
            unsigned a0 = Qs[rbase*LQ + k0 + lc];
            unsigned a1 = Qs[(rbase+8)*LQ + k0 + lc];
            unsigned a2 = Qs[rbase*LQ + k0 + lc + 4];
            unsigned a3 = Qs[(rbase+8)*LQ + k0 + lc + 4];
            #pragma unroll
            for (int nt = 0; nt < 4; nt++) {
                int nc = nt*8 + lr;
                unsigned b0 = Ks[nc*LK + k0 + lc];
                unsigned b1 = Ks[nc*LK + k0 + lc + 4];
                MMA_TF32(s[nt][0],s[nt][1],s[nt][2],s[nt][3], a0,a1,a2,a3, b0,b1);
            }
        }

        {
            int lim0 = gq0 - kb;
            int lim1 = gq1 - kb;
            float p0[8], p1[8];
            float mx0 = -1e30f, mx1 = -1e30f;
            #pragma unroll
            for (int nt = 0; nt < 4; nt++) {
                int c0 = nt*8 + 2*lc, c1 = c0 + 1;
                p0[nt*2]   = (c0 <= lim0) ? s[nt][0]*scale : -1e30f;
                p0[nt*2+1] = (c1 <= lim0) ? s[nt][1]*scale : -1e30f;
                p1[nt*2]   = (c0 <= lim1) ? s[nt][2]*scale : -1e30f;
                p1[nt*2+1] = (c1 <= lim1) ? s[nt][3]*scale : -1e30f;
                mx0 = fmaxf(mx0, fmaxf(p0[nt*2], p0[nt*2+1]));
                mx1 = fmaxf(mx1, fmaxf(p1[nt*2], p1[nt*2+1]));
            }
            mx0 = fmaxf(mx0, __shfl_xor_sync(0xffffffffu, mx0, 1));
            mx0 = fmaxf(mx0, __shfl_xor_sync(0xffffffffu, mx0, 2));
            mx1 = fmaxf(mx1, __shfl_xor_sync(0xffffffffu, mx1, 1));
            mx1 = fmaxf(mx1, __shfl_xor_sync(0xffffffffu, mx1, 2));
            float mn0 = fmaxf(m0, mx0), mn1 = fmaxf(m1, mx1);
            float al0 = __expf(m0 - mn0), al1 = __expf(m1 - mn1);
            float ss0 = 0.f, ss1 = 0.f;
            #pragma unroll
            for (int nt = 0; nt < 4; nt++) {
                int c0 = nt*8 + 2*lc, c1 = c0 + 1;
                float e00 = (c0 <= lim0) ? __expf(p0[nt*2]   - mn0) : 0.f;
                float e01 = (c1 <= lim0) ? __expf(p0[nt*2+1] - mn0) : 0.f;
                float e10 = (c0 <= lim1) ? __expf(p1[nt*2]   - mn1) : 0.f;
                float e11 = (c1 <= lim1) ? __expf(p1[nt*2+1] - mn1) : 0.f;
                Pu[rbase*LP + c0]     = f2tf(e00);
                Pu[rbase*LP + c1]     = f2tf(e01);
                Pu[(rbase+8)*LP + c0] = f2tf(e10);
                Pu[(rbase+8)*LP + c1] = f2tf(e11);
                ss0 += e00 + e01;
                ss1 += e10 + e11;
            }
            ss0 += __shfl_xor_sync(0xffffffffu, ss0, 1);
            ss0 += __shfl_xor_sync(0xffffffffu, ss0, 2);
            ss1 += __shfl_xor_sync(0xffffffffu, ss1, 1);
            ss1 += __shfl_xor_sync(0xffffffffu, ss1, 2);
            l0 = l0 * al0 + ss0;  m0 = mn0;
            l1 = l1 * al1 + ss1;  m1 = mn1;
            #pragma unroll
            for (int j = 0; j < 16; j++) {
                o[j][0] *= al0; o[j][1] *= al0;
                o[j][2] *= al1; o[j][3] *= al1;
            }
        }
        __syncwarp();

        #pragma unroll
        for (int kk = 0; kk < 4; kk++) {
            int k0 = kk*8;
            unsigned a0 = Pu[rbase*LP + k0 + lc];
            unsigned a1 = Pu[(rbase+8)*LP + k0 + lc];
            unsigned a2 = Pu[rbase*LP + k0 + lc + 4];
            unsigned a3 = Pu[(rbase+8)*LP + k0 + lc + 4];
            #pragma unroll
            for (int j = 0; j < 16; j++) {
                int vc = j*8 + lr;
                unsigned b0 = Vs[(k0 + lc)*LV + vc];
                unsigned b1 = Vs[(k0 + lc + 4)*LV + vc];
                MMA_TF32(o[j][0],o[j][1],o[j][2],o[j][3], a0,a1,a2,a3, b0,b1);
            }
        }
    }

    int b = bk >> 3, jslot = bk & 7;
    float w_lo = HWp[((size_t)(b*SEQ + gq0)) * KSEL + jslot] / l0;
    float w_hi = HWp[((size_t)(b*SEQ + gq1)) * KSEL + jslot] / l1;
    #pragma unroll
    for (int j = 0; j < 16; j++) {
        int cb = j*8 + 2*lc;
        size_t off0 = (((size_t)(b*SEQ + gq0)) * KSEL + jslot) * HD + cb;
        size_t off1 = (((size_t)(b*SEQ + gq1)) * KSEL + jslot) * HD + cb;
        float2 v0 = make_float2(tfround(o[j][0]*w_lo), tfround(o[j][1]*w_lo));
        float2 v1 = make_float2(tfround(o[j][2]*w_hi), tfround(o[j][3]*w_hi));
        *(float2*)&Out[off0] = v0;
        *(float2*)&Out[off1] = v1;
    }
}

// ---------------- aux loss + head_counts tail ----------------
__global__ void finalize_kernel(float* __restrict__ out, int out_size) {
    int base = NTOK * EMB;
    int extra = out_size - base;
    if (extra <= 0) return;
    bool has_aux = (extra == BATCH*NH + 1) || (extra == 1);
    int zend = has_aux ? out_size - 1 : out_size;
    int gtid = blockIdx.x * blockDim.x + threadIdx.x;
    for (int i = base + gtid; i < zend; i += gridDim.x * blockDim.x) out[i] = 0.f;
    if (gtid == 0 && has_aux) {
        float aux = 0.f;
        for (int b = 0; b < BATCH; b++) {
            float sb = 0.f;
            for (int h = 0; h < NH; h++)
                sb += (g_facc[b*NH + h] / (float)SEQ) * (g_pacc[b*NH + h] / (float)SEQ);
            aux += sb;
        }
        aux = (float)NH * aux / (float)BATCH - 0.01f * (g_ent[0] / (float)(BATCH*SEQ));
        out[out_size - 1] = aux;
    }
}

// ---------------- launcher ----------------
extern "C" void kernel_launch(void* const* d_in, const int* in_sizes, int n_in,
                              void* d_out, int out_size)
{
    (void)in_sizes; (void)n_in;
    const float* x  = (const float*)d_in[0];
    const float* Wq = (const float*)d_in[1];
    const float* Wk = (const float*)d_in[2];
    const float* Wv = (const float*)d_in[3];
    const float* Wr = (const float*)d_in[4];
    const float* Wo = (const float*)d_in[5];
    float* out = (float*)d_out;

    float *p_q, *p_k, *p_v, *p_attn, *p_hw;
    float *p_xr, *p_wq, *p_wk, *p_wv, *p_wo;
    cudaGetSymbolAddress((void**)&p_q,    g_q);
    cudaGetSymbolAddress((void**)&p_k,    g_k);
    cudaGetSymbolAddress((void**)&p_v,    g_v);
    cudaGetSymbolAddress((void**)&p_attn, g_attn);
    cudaGetSymbolAddress((void**)&p_hw,   g_hw);
    cudaGetSymbolAddress((void**)&p_xr,   g_xr);
    cudaGetSymbolAddress((void**)&p_wq,   g_wq);
    cudaGetSymbolAddress((void**)&p_wk,   g_wk);
    cudaGetSymbolAddress((void**)&p_wv,   g_wv);
    cudaGetSymbolAddress((void**)&p_wo,   g_wo);

    size_t gemm_smem = (size_t)(2*BM*LDA + 2*BKt*LDB) * sizeof(float);
    cudaFuncSetAttribute(moh_proj_kernel, cudaFuncAttributeMaxDynamicSharedMemorySize,
                         (int)gemm_smem);
    cudaFuncSetAttribute(tf32_gemm_kernel, cudaFuncAttributeMaxDynamicSharedMemorySize,
                         (int)gemm_smem);
    size_t flash_smem = (size_t)(128*LQ + 2*32*LK + 2*32*LV + 128*LP) * sizeof(float);
    cudaFuncSetAttribute(flash_tc_kernel, cudaFuncAttributeMaxDynamicSharedMemorySize,
                         (int)flash_smem);

    zero_stats_kernel<<<1, 128>>>();
    router_kernel<<<NTOK, 128>>>(x, Wr);

    tfround_kernel<<<512, 256>>>((const float4*)x,  (float4*)p_xr, NTOK*EMB/4);
    dim3 g3(512, 3);
    tfround3_kernel<<<g3, 256>>>((const float4*)Wq, (const float4*)Wk, (const float4*)Wv,
                                 (float4*)p_wq, (float4*)p_wk, (float4*)p_wv, EMB*HDALL/4);
    tfround_kernel<<<512, 256>>>((const float4*)Wo, (float4*)p_wo, KD*EMB/4);

    dim3 gproj(NTOK/BM, NH, 3);
    moh_proj_kernel<<<gproj, 256, gemm_smem>>>(p_xr, p_wq, p_wk, p_wv, p_q, p_k, p_v);

    dim3 gflash(SEQ/128, BATCH*KSEL);   // (16, 16)
    flash_tc_kernel<<<gflash, 256, flash_smem>>>(p_q, p_k, p_v, p_hw, p_attn);

    dim3 gout(EMB/BN, NTOK/BM);
    tf32_gemm_kernel<<<gout, 256, gemm_smem>>>(p_attn, p_wo, out, NTOK, EMB, EMB);

    finalize_kernel<<<32, 256>>>(out, out_size);
}